// round 1
// baseline (speedup 1.0000x reference)
#include <cuda_runtime.h>
#include <cstdint>
#include <cstddef>

#define BB 4
#define NN 4096
#define MM 4096
#define CC 128
#define CAP 512

#define THR2 0.04f
#define NEG_INV_SCALE (-99.9999000001f)   /* -(1/(0.01+1e-8)) */

// ---------------- scratch (device globals; no allocation) ----------------
__device__ int    g_mask_i32;

__device__ float2 g_cs_loc[BB*NN];
__device__ int    g_cs_idx[BB*NN];
__device__ int    g_cs_cnt[BB];
__device__ float2 g_ct_loc[BB*MM];
__device__ int    g_ct_idx[BB*MM];
__device__ int    g_ct_cnt[BB];

__device__ int2   g_rowlist[(size_t)BB*MM*CAP];   // {src idx n, logK bits}
__device__ int    g_rowcnt[BB*MM];
__device__ int2   g_collist[(size_t)BB*NN*CAP];   // {tgt idx m, logK bits}
__device__ int    g_colcnt[BB*NN];

__device__ float  g_u[BB*MM];
__device__ float  g_v[BB*NN];
__device__ int    g_count0[BB];                   // rows with u == +1e9 exactly

__device__ __forceinline__ bool mask_at(const void* p, int i) {
    return g_mask_i32 ? (((const int*)p)[i] != 0)
                      : (((const unsigned char*)p)[i] != 0);
}

// ---------------- 0: detect mask dtype (bool-u8 vs int32) ----------------
__global__ void k_detect(const unsigned char* __restrict__ sm) {
    __shared__ int flag;
    if (threadIdx.x == 0) flag = 0;
    __syncthreads();
    int acc = 0;
    // First 16384 bytes are safe to read under either layout.
    for (int p = threadIdx.x; p < 16384; p += blockDim.x)
        if (p & 3) acc |= sm[p];
    if (acc) atomicOr(&flag, 1);
    __syncthreads();
    if (threadIdx.x == 0) g_mask_i32 = (flag == 0);
}

// ---------------- 1: compact valid source/target locations ---------------
__global__ void k_compact(const float* __restrict__ slocs,
                          const float* __restrict__ tlocs,
                          const void* __restrict__ smask,
                          const void* __restrict__ tmask) {
    int w = threadIdx.x >> 5, lane = threadIdx.x & 31;
    int which = w >> 2, b = w & 3;
    const void*   mk     = which ? tmask : smask;
    const float2* loc    = (const float2*)(which ? tlocs : slocs);
    float2*       outloc = which ? g_ct_loc : g_cs_loc;
    int*          outidx = which ? g_ct_idx : g_cs_idx;
    int*          outcnt = which ? g_ct_cnt : g_cs_cnt;
    int base = b * NN;
    int cnt = 0;
    for (int i0 = 0; i0 < NN; i0 += 32) {
        int i = i0 + lane;
        bool m = mask_at(mk, base + i);
        unsigned bal = __ballot_sync(0xffffffffu, m);
        if (m) {
            int pos = cnt + __popc(bal & ((1u << lane) - 1u));
            outloc[base + pos] = loc[base + i];
            outidx[base + pos] = i;
        }
        cnt += __popc(bal);
    }
    if (lane == 0) outcnt[b] = cnt;
}

// ---------------- 2: build row adjacency (one warp per target row) -------
__global__ void k_build_rows(const float* __restrict__ tlocs,
                             const void* __restrict__ tmask) {
    int gw = (blockIdx.x * blockDim.x + threadIdx.x) >> 5;
    int lane = threadIdx.x & 31;
    if (gw >= BB * MM) return;
    int b = gw >> 12, base = b * NN;
    if (!mask_at(tmask, gw)) { if (!lane) g_rowcnt[gw] = 0; return; }
    float2 t = ((const float2*)tlocs)[gw];
    int ns = g_cs_cnt[b];
    int2* lst = g_rowlist + (size_t)gw * CAP;
    int cnt = 0;
    for (int j0 = 0; j0 < ns; j0 += 32) {
        int j = j0 + lane;
        bool pr = j < ns;
        float2 s = pr ? g_cs_loc[base + j] : make_float2(1e30f, 1e30f);
        float dx = t.x - s.x, dy = t.y - s.y;
        float d2 = __fadd_rn(__fmul_rn(dx, dx), __fmul_rn(dy, dy));
        bool val = pr && (d2 < THR2);
        unsigned bal = __ballot_sync(0xffffffffu, val);
        if (val) {
            int pos = cnt + __popc(bal & ((1u << lane) - 1u));
            if (pos < CAP)
                lst[pos] = make_int2(g_cs_idx[base + j],
                                     __float_as_int(__fmul_rn(d2, NEG_INV_SCALE)));
        }
        cnt += __popc(bal);
    }
    if (!lane) g_rowcnt[gw] = min(cnt, CAP);
}

// ---------------- 3: build col adjacency (one warp per source col) -------
__global__ void k_build_cols(const float* __restrict__ slocs,
                             const void* __restrict__ smask) {
    int gw = (blockIdx.x * blockDim.x + threadIdx.x) >> 5;
    int lane = threadIdx.x & 31;
    if (gw >= BB * NN) return;
    int b = gw >> 12, base = b * MM;
    if (!mask_at(smask, gw)) { if (!lane) g_colcnt[gw] = 0; return; }
    float2 s = ((const float2*)slocs)[gw];
    int nt = g_ct_cnt[b];
    int2* lst = g_collist + (size_t)gw * CAP;
    int cnt = 0;
    for (int j0 = 0; j0 < nt; j0 += 32) {
        int j = j0 + lane;
        bool pr = j < nt;
        float2 t = pr ? g_ct_loc[base + j] : make_float2(1e30f, 1e30f);
        float dx = t.x - s.x, dy = t.y - s.y;
        float d2 = __fadd_rn(__fmul_rn(dx, dx), __fmul_rn(dy, dy));
        bool val = pr && (d2 < THR2);
        unsigned bal = __ballot_sync(0xffffffffu, val);
        if (val) {
            int pos = cnt + __popc(bal & ((1u << lane) - 1u));
            if (pos < CAP)
                lst[pos] = make_int2(g_ct_idx[base + j],
                                     __float_as_int(__fmul_rn(d2, NEG_INV_SCALE)));
        }
        cnt += __popc(bal);
    }
    if (!lane) g_colcnt[gw] = min(cnt, CAP);
}

// ---------------- 4: count0 per batch + zero v ----------------------------
__global__ void k_prep() {
    __shared__ int red[256];
    int b = blockIdx.x;
    int c = 0;
    for (int m = threadIdx.x; m < MM; m += blockDim.x)
        c += (g_rowcnt[b * MM + m] > 0);
    red[threadIdx.x] = c;
    __syncthreads();
    for (int s = 128; s; s >>= 1) {
        if (threadIdx.x < s) red[threadIdx.x] += red[threadIdx.x + s];
        __syncthreads();
    }
    if (threadIdx.x == 0) g_count0[b] = MM - red[0];
    for (int n = threadIdx.x; n < NN; n += blockDim.x) g_v[b * NN + n] = 0.0f;
}

// ---------------- 5: u update (one warp per target row) -------------------
__global__ void k_u() {
    int gw = (blockIdx.x * blockDim.x + threadIdx.x) >> 5;
    int lane = threadIdx.x & 31;
    if (gw >= BB * MM) return;
    int b = gw >> 12;
    int cnt = g_rowcnt[gw];
    if (cnt == 0) { if (!lane) g_u[gw] = 1e9f; return; }
    const int2* lst = g_rowlist + (size_t)gw * CAP;
    const float* v = g_v + b * NN;
    float mx = __int_as_float(0xff800000);  // -inf
    for (int e = lane; e < cnt; e += 32) {
        int2 p = lst[e];
        mx = fmaxf(mx, __int_as_float(p.y) + v[p.x]);
    }
    for (int o = 16; o; o >>= 1) mx = fmaxf(mx, __shfl_xor_sync(0xffffffffu, mx, o));
    float s = 0.f;
    for (int e = lane; e < cnt; e += 32) {
        int2 p = lst[e];
        s += __expf(__int_as_float(p.y) + v[p.x] - mx);
    }
    for (int o = 16; o; o >>= 1) s += __shfl_xor_sync(0xffffffffu, s, o);
    if (!lane) g_u[gw] = -(mx + __logf(s));
}

// ---------------- 6: v update (one warp per source col) -------------------
// Entries from rows with u==+1e9 contribute t = -1e9 + 1e9 = 0 exactly in the
// reference fp32 arithmetic; there are count0 of them for EVERY column.
__global__ void k_v(const void* __restrict__ smask) {
    int gw = (blockIdx.x * blockDim.x + threadIdx.x) >> 5;
    int lane = threadIdx.x & 31;
    if (gw >= BB * NN) return;
    int b = gw >> 12;
    if (!mask_at(smask, gw)) { if (!lane) g_v[gw] = 0.f; return; }
    int cnt = g_colcnt[gw];
    float c0 = (float)g_count0[b];
    if (cnt == 0) {
        if (!lane) g_v[gw] = (c0 > 0.f) ? -__logf(c0) : 1e9f;
        return;
    }
    const int2* lst = g_collist + (size_t)gw * CAP;
    const float* u = g_u + b * MM;
    float mx = __int_as_float(0xff800000);
    for (int e = lane; e < cnt; e += 32) {
        int2 p = lst[e];
        mx = fmaxf(mx, __int_as_float(p.y) + u[p.x]);
    }
    for (int o = 16; o; o >>= 1) mx = fmaxf(mx, __shfl_xor_sync(0xffffffffu, mx, o));
    if (c0 > 0.f) mx = fmaxf(mx, 0.0f);
    float s = 0.f;
    for (int e = lane; e < cnt; e += 32) {
        int2 p = lst[e];
        s += __expf(__int_as_float(p.y) + u[p.x] - mx);
    }
    for (int o = 16; o; o >>= 1) s += __shfl_xor_sync(0xffffffffu, s, o);
    if (!lane) {
        float st = s + ((c0 > 0.f) ? c0 * __expf(-mx) : 0.f);
        g_v[gw] = -(mx + __logf(st));
    }
}

// ---------------- 7: attn weights + feature gather (warp per row) --------
__global__ void k_out(const float* __restrict__ feats, float* __restrict__ out) {
    __shared__ int   s_idx[8][CAP];
    __shared__ float s_w[8][CAP];
    int wid = threadIdx.x >> 5, lane = threadIdx.x & 31;
    int gw = (blockIdx.x * blockDim.x + threadIdx.x) >> 5;
    if (gw >= BB * MM) return;
    int b = gw >> 12;
    int cnt = g_rowcnt[gw];
    float4 acc = make_float4(0.f, 0.f, 0.f, 0.f);
    if (cnt > 0) {
        const int2* lst = g_rowlist + (size_t)gw * CAP;
        const float* v = g_v + b * NN;
        float um = g_u[gw];
        for (int e = lane; e < cnt; e += 32) {
            int2 p = lst[e];
            s_idx[wid][e] = p.x;
            s_w[wid][e]   = __expf(__int_as_float(p.y) + um + v[p.x]);
        }
        __syncwarp();
        const float4* f4 = ((const float4*)feats) + (size_t)b * NN * (CC / 4);
        int e = 0;
        for (; e + 4 <= cnt; e += 4) {
            int   n0 = s_idx[wid][e],     n1 = s_idx[wid][e + 1];
            int   n2 = s_idx[wid][e + 2], n3 = s_idx[wid][e + 3];
            float w0 = s_w[wid][e],       w1 = s_w[wid][e + 1];
            float w2 = s_w[wid][e + 2],   w3 = s_w[wid][e + 3];
            float4 a0 = f4[(size_t)n0 * 32 + lane];
            float4 a1 = f4[(size_t)n1 * 32 + lane];
            float4 a2 = f4[(size_t)n2 * 32 + lane];
            float4 a3 = f4[(size_t)n3 * 32 + lane];
            acc.x = fmaf(w0, a0.x, acc.x); acc.y = fmaf(w0, a0.y, acc.y);
            acc.z = fmaf(w0, a0.z, acc.z); acc.w = fmaf(w0, a0.w, acc.w);
            acc.x = fmaf(w1, a1.x, acc.x); acc.y = fmaf(w1, a1.y, acc.y);
            acc.z = fmaf(w1, a1.z, acc.z); acc.w = fmaf(w1, a1.w, acc.w);
            acc.x = fmaf(w2, a2.x, acc.x); acc.y = fmaf(w2, a2.y, acc.y);
            acc.z = fmaf(w2, a2.z, acc.z); acc.w = fmaf(w2, a2.w, acc.w);
            acc.x = fmaf(w3, a3.x, acc.x); acc.y = fmaf(w3, a3.y, acc.y);
            acc.z = fmaf(w3, a3.z, acc.z); acc.w = fmaf(w3, a3.w, acc.w);
        }
        for (; e < cnt; e++) {
            int n = s_idx[wid][e];
            float w = s_w[wid][e];
            float4 a = f4[(size_t)n * 32 + lane];
            acc.x = fmaf(w, a.x, acc.x); acc.y = fmaf(w, a.y, acc.y);
            acc.z = fmaf(w, a.z, acc.z); acc.w = fmaf(w, a.w, acc.w);
        }
    }
    ((float4*)out)[(size_t)gw * 32 + lane] = acc;
}

// ---------------- launch ----------------
extern "C" void kernel_launch(void* const* d_in, const int* in_sizes, int n_in,
                              void* d_out, int out_size) {
    const float* feats = (const float*)d_in[0];
    const float* slocs = (const float*)d_in[1];
    const float* tlocs = (const float*)d_in[2];
    const void*  smask = d_in[3];
    const void*  tmask = d_in[4];
    float* out = (float*)d_out;

    k_detect<<<1, 256>>>((const unsigned char*)smask);
    k_compact<<<1, 256>>>(slocs, tlocs, smask, tmask);
    k_build_rows<<<(BB * MM) / 8, 256>>>(tlocs, tmask);
    k_build_cols<<<(BB * NN) / 8, 256>>>(slocs, smask);
    k_prep<<<BB, 256>>>();
    for (int it = 0; it < 3; it++) {
        k_u<<<(BB * MM) / 8, 256>>>();
        k_v<<<(BB * NN) / 8, 256>>>(smask);
    }
    k_out<<<(BB * MM) / 8, 256>>>(feats, out);
}